// round 11
// baseline (speedup 1.0000x reference)
#include <cuda_runtime.h>
#include <cuda_fp16.h>
#include <math.h>

#define NN 100000
#define NE 1600000
#define DD 128
#define HH 128
#define HO 64
#define NCLS 10
#define NG 128

// ---------------- device scratch (static, zero-init; no runtime alloc) ------
// INVARIANTS (hold at entry of every call; statics start zeroed, and every
// call re-establishes them): g_deg == 0 (re-zeroed in k_final),
// g_base_ctr == 0 (reset in k_final). g_pool is zeroed inside k_gemm2.
__device__ int    g_col[NE];
__device__ int    g_rank[NE];             // rank of edge within its dst segment
__device__ int    g_batch[NN];
__device__ int    g_deg[NN];
__device__ float  g_dis[NN];
__device__ int    g_rowptr[NN];
__device__ int    g_base_ctr;
__device__ __half g_W12T[HH * DD];        // (lin1_w @ conv1_w)^T, fp16 n-major
__device__ float  g_b12[HH];
__device__ __half g_W2T[HO * DD];         // conv2_w^T, fp16 n-major
__device__ __half g_h2[(size_t)NN * HH];  // (x@W12 + b12) * dis[row]  (fp16)
__device__ __half g_h3[(size_t)NN * HH];  // after agg1 + bias + dropout + relu (fp16)
__device__ __half g_h4[(size_t)NN * HO];  // (h3@conv2_w) * dis[row]   (fp16)
__device__ float  g_pool[NG * HO];

// ---------------- dtype detection (per-block, cheap: 64 sampled loads) ------
// int64 arrays have zero high words at odd int32 positions; int32 node ids /
// sorted upper-half batch ids are essentially never all zero over 64 samples.
__device__ __forceinline__ int detect_e64(const unsigned int* __restrict__ ew, long esz) {
    int f = 0;
#pragma unroll 8
    for (int i = 0; i < 64; i++) {
        long idx = 1 + 2 * ((long)i * ((esz - 2) / 2) / 64);
        if (idx >= esz) idx = esz - 1;
        if (!(idx & 1)) idx--;
        if (idx >= 0 && idx < esz && ew[idx] != 0u) f = 1;
    }
    return !f;
}
__device__ __forceinline__ int detect_b64(const unsigned int* __restrict__ bw, long bsz) {
    int f = 0;
#pragma unroll 8
    for (int i = 0; i < 64; i++) {
        long j = bsz / 2 + ((long)i * (bsz / 2) / 64);
        if (!(j & 1)) j++;
        if (j < bsz && bw[j] != 0u) f = 1;
    }
    return !f;
}

// ---------------- warp mma helper -------------------------------------------
__device__ __forceinline__ void mma16816(float* c, const unsigned* a, const unsigned* b) {
    asm volatile(
        "mma.sync.aligned.m16n8k16.row.col.f32.f16.f16.f32 "
        "{%0,%1,%2,%3}, {%4,%5,%6,%7}, {%8,%9}, {%0,%1,%2,%3};"
        : "+f"(c[0]), "+f"(c[1]), "+f"(c[2]), "+f"(c[3])
        : "r"(a[0]), "r"(a[1]), "r"(a[2]), "r"(a[3]), "r"(b[0]), "r"(b[1]));
}

// ---------------- degree histogram (returns rank!) + batch convert ----------
__global__ void k_prep(const void* __restrict__ ep, long esz,
                       const void* __restrict__ bp, long bsz) {
    int e64 = detect_e64((const unsigned int*)ep, esz);
    int b64 = detect_b64((const unsigned int*)bp, bsz);
    long stride = (long)gridDim.x * blockDim.x;
    long i0 = (long)blockIdx.x * blockDim.x + threadIdx.x;
    if (e64) {
        const long long* p = (const long long*)ep;
        for (long i = i0; i < NE; i += stride)
            g_rank[i] = atomicAdd(&g_deg[(int)p[NE + i]], 1);
    } else {
        const int* p = (const int*)ep;
        for (long i = i0; i < NE; i += stride)
            g_rank[i] = atomicAdd(&g_deg[p[NE + i]], 1);
    }
    if (b64) {
        const long long* p = (const long long*)bp;
        for (long i = i0; i < NN; i += stride) g_batch[i] = (int)p[i];
    } else {
        const int* p = (const int*)bp;
        for (long i = i0; i < NN; i += stride) g_batch[i] = p[i];
    }
}

// ---------------- merged: unordered scan (blocks < SB) + weight fold --------
#define SCAN_BLOCKS 98
#define FOLD_ITEMS (DD * HH + HH + HH * HO)
__global__ void k_scan_fold(const float* __restrict__ l1w, const float* __restrict__ l1b,
                            const float* __restrict__ c1w, const float* __restrict__ c2w) {
    if (blockIdx.x < SCAN_BLOCKS) {
        __shared__ int s[1024];
        __shared__ int sbase;
        int t = threadIdx.x;
        int i = blockIdx.x * 1024 + t;
        int v = (i < NN) ? g_deg[i] : 0;
        s[t] = v;
        __syncthreads();
        for (int o = 1; o < 1024; o <<= 1) {
            int add = (t >= o) ? s[t - o] : 0;
            __syncthreads();
            if (t >= o) s[t] += add;
            __syncthreads();
        }
        if (t == 1023) sbase = atomicAdd(&g_base_ctr, s[1023]);
        __syncthreads();
        if (i < NN) {
            g_rowptr[i] = s[t] - v + sbase;
            g_dis[i] = rsqrtf((float)(v + 1));  // +1 for the self loop
        }
    } else {
        int idx = (blockIdx.x - SCAN_BLOCKS) * 1024 + threadIdx.x;
        if (idx < DD * HH) {
            int k = idx / HH, m = idx % HH;
            float s = 0.f;
            for (int j = 0; j < DD; j++) s += l1w[k * DD + j] * c1w[j * HH + m];
            g_W12T[m * DD + k] = __float2half(s);
        } else if (idx < DD * HH + HH) {
            int m = idx - DD * HH;
            float s = 0.f;
            for (int j = 0; j < DD; j++) s += l1b[j] * c1w[j * HH + m];
            g_b12[m] = s;
        } else if (idx < FOLD_ITEMS) {
            int j = idx - (DD * HH + HH);
            int k = j / HO, n = j % HO;
            g_W2T[n * DD + k] = __float2half(c2w[k * HO + n]);
        }
    }
}

// ---------------- CSR fill (atomic-free, SEPARATE kernel: low regs, full occ)
__global__ void k_fill(const void* __restrict__ ep, long esz) {
    int e64 = detect_e64((const unsigned int*)ep, esz);
    long stride = (long)gridDim.x * blockDim.x;
    long i0 = (long)blockIdx.x * blockDim.x + threadIdx.x;
    if (e64) {
        const long long* p = (const long long*)ep;
        for (long i = i0; i < NE; i += stride) {
            int s = (int)p[i];
            int d = (int)p[NE + i];
            g_col[g_rowptr[d] + g_rank[i]] = s;
        }
    } else {
        const int* p = (const int*)ep;
        for (long i = i0; i < NE; i += stride) {
            int s = p[i];
            int d = p[NE + i];
            g_col[g_rowptr[d] + g_rank[i]] = s;
        }
    }
}

// ---------------- HMMA GEMM body: out[n][MOUT] = (A[n][128] @ W (+bias))*dis[n]
// MODE 1: A = x (fp32), W = g_W12T, bias = g_b12, out = g_h2
// MODE 2: A = g_h3 (fp16), W = g_W2T, no bias,    out = g_h4
template <int MOUT, int MODE>
__device__ __forceinline__ void gemm_body(const float* __restrict__ x, int row0) {
    constexpr int ROWS = 64;
    constexpr int KPAD = 72;                 // 64 + 8 halves pad -> conflict-free
    constexpr int NW = MOUT / 4;             // warp n-width (32 or 16)
    constexpr int NT = NW / 8;               // n8-tiles per warp (4 or 2)
    __shared__ __half As[ROWS][KPAD];
    __shared__ __half Ws[MOUT][KPAD];

    int tid = threadIdx.x;
    int wid = tid >> 5, lane = tid & 31;
    int gid = lane >> 2, tg = lane & 3;
    int wm = wid >> 2, wn = wid & 3;         // 2 x 4 warp grid
    __half* out = (MODE == 1) ? g_h2 : g_h4;
    const __half* WT = (MODE == 1) ? g_W12T : g_W2T;

    float acc[2][NT][4];
#pragma unroll
    for (int mt = 0; mt < 2; mt++)
#pragma unroll
        for (int nt = 0; nt < NT; nt++)
#pragma unroll
            for (int q = 0; q < 4; q++) acc[mt][nt][q] = 0.f;

#pragma unroll
    for (int ch = 0; ch < 2; ch++) {
        int k0 = ch * 64;
        if (MODE == 1) {
#pragma unroll
            for (int idx = tid; idx < ROWS * 16; idx += 256) {
                int r = idx >> 4, q = idx & 15;
                int gr = row0 + r;
                float4 v = make_float4(0.f, 0.f, 0.f, 0.f);
                if (gr < NN) v = *(const float4*)&x[(size_t)gr * DD + k0 + q * 4];
                *(__half2*)&As[r][q * 4]     = __floats2half2_rn(v.x, v.y);
                *(__half2*)&As[r][q * 4 + 2] = __floats2half2_rn(v.z, v.w);
            }
        } else {
#pragma unroll
            for (int idx = tid; idx < ROWS * 8; idx += 256) {
                int r = idx >> 3, q = idx & 7;
                int gr = row0 + r;
                uint4 v = make_uint4(0u, 0u, 0u, 0u);
                if (gr < NN) v = *(const uint4*)&g_h3[(size_t)gr * HH + k0 + q * 8];
                *(uint4*)&As[r][q * 8] = v;
            }
        }
#pragma unroll
        for (int idx = tid; idx < MOUT * 8; idx += 256) {
            int n = idx >> 3, q = idx & 7;
            *(uint4*)&Ws[n][q * 8] = *(const uint4*)&WT[n * DD + k0 + q * 8];
        }
        __syncthreads();
#pragma unroll
        for (int ks = 0; ks < 4; ks++) {
            int kk = ks * 16;
            unsigned af[2][4];
#pragma unroll
            for (int mt = 0; mt < 2; mt++) {
                int r = wm * 32 + mt * 16 + gid;
                af[mt][0] = *(unsigned*)&As[r][kk + tg * 2];
                af[mt][1] = *(unsigned*)&As[r + 8][kk + tg * 2];
                af[mt][2] = *(unsigned*)&As[r][kk + tg * 2 + 8];
                af[mt][3] = *(unsigned*)&As[r + 8][kk + tg * 2 + 8];
            }
            unsigned bf[NT][2];
#pragma unroll
            for (int nt = 0; nt < NT; nt++) {
                int n = wn * NW + nt * 8 + gid;
                bf[nt][0] = *(unsigned*)&Ws[n][kk + tg * 2];
                bf[nt][1] = *(unsigned*)&Ws[n][kk + tg * 2 + 8];
            }
#pragma unroll
            for (int mt = 0; mt < 2; mt++)
#pragma unroll
                for (int nt = 0; nt < NT; nt++)
                    mma16816(acc[mt][nt], af[mt], bf[nt]);
        }
        __syncthreads();
    }

#pragma unroll
    for (int mt = 0; mt < 2; mt++) {
        int r_lo = row0 + wm * 32 + mt * 16 + gid;
        int r_hi = r_lo + 8;
        float dlo = (r_lo < NN) ? g_dis[r_lo] : 0.f;
        float dhi = (r_hi < NN) ? g_dis[r_hi] : 0.f;
#pragma unroll
        for (int nt = 0; nt < NT; nt++) {
            int n = wn * NW + nt * 8 + tg * 2;
            float b0 = 0.f, b1 = 0.f;
            if (MODE == 1) { b0 = g_b12[n]; b1 = g_b12[n + 1]; }
            if (r_lo < NN)
                *(__half2*)&out[(size_t)r_lo * MOUT + n] =
                    __floats2half2_rn((acc[mt][nt][0] + b0) * dlo,
                                      (acc[mt][nt][1] + b1) * dlo);
            if (r_hi < NN)
                *(__half2*)&out[(size_t)r_hi * MOUT + n] =
                    __floats2half2_rn((acc[mt][nt][2] + b0) * dhi,
                                      (acc[mt][nt][3] + b1) * dhi);
        }
    }
}

#define GB1 ((NN + 63) / 64)

// ---------------- GEMM1 (separate kernel, full tensor occupancy) ------------
__global__ void __launch_bounds__(256) k_gemm1(const float* __restrict__ x) {
    gemm_body<HH, 1>(x, blockIdx.x * 64);
}

// ---------------- GEMM2 + pool zeroing (one extra trivial block) ------------
__global__ void __launch_bounds__(256) k_gemm2(void) {
    if (blockIdx.x < GB1) {
        gemm_body<HO, 2>(nullptr, blockIdx.x * 64);
    } else {
        for (int j = threadIdx.x; j < NG * HO; j += 256) g_pool[j] = 0.f;
    }
}

// ---------------- aggregation 1 (gather-sum fp16, 128 feats) + bias/drop/relu
__global__ void k_agg1(const float* __restrict__ c1b, const float* __restrict__ du) {
    int node = (blockIdx.x * blockDim.x + threadIdx.x) >> 5;
    int lane = threadIdx.x & 31;
    if (node >= NN) return;
    float di = g_dis[node];
    size_t base = (size_t)node * HH + lane * 4;
    uint2 rs = *(const uint2*)&g_h2[base];  // self loop term
    float2 f0 = __half22float2(*(__half2*)&rs.x);
    float2 f1 = __half22float2(*(__half2*)&rs.y);
    float ax = f0.x, ay = f0.y, az = f1.x, aw = f1.y;
    int b = g_rowptr[node];
    int e = b + g_deg[node];
    int t = b;
    for (; t + 8 <= e; t += 8) {
        int si[8];
#pragma unroll
        for (int q = 0; q < 8; q++) si[q] = g_col[t + q];
        uint2 r[8];
#pragma unroll
        for (int q = 0; q < 8; q++)
            r[q] = *(const uint2*)&g_h2[(size_t)si[q] * HH + lane * 4];
#pragma unroll
        for (int q = 0; q < 8; q++) {
            float2 a = __half22float2(*(__half2*)&r[q].x);
            float2 bb = __half22float2(*(__half2*)&r[q].y);
            ax += a.x; ay += a.y; az += bb.x; aw += bb.y;
        }
    }
    for (; t + 4 <= e; t += 4) {
        int s0 = g_col[t], s1 = g_col[t + 1], s2 = g_col[t + 2], s3 = g_col[t + 3];
        uint2 r0 = *(const uint2*)&g_h2[(size_t)s0 * HH + lane * 4];
        uint2 r1 = *(const uint2*)&g_h2[(size_t)s1 * HH + lane * 4];
        uint2 r2 = *(const uint2*)&g_h2[(size_t)s2 * HH + lane * 4];
        uint2 r3 = *(const uint2*)&g_h2[(size_t)s3 * HH + lane * 4];
        float2 a0 = __half22float2(*(__half2*)&r0.x), b0 = __half22float2(*(__half2*)&r0.y);
        float2 a1 = __half22float2(*(__half2*)&r1.x), b1 = __half22float2(*(__half2*)&r1.y);
        float2 a2 = __half22float2(*(__half2*)&r2.x), b2 = __half22float2(*(__half2*)&r2.y);
        float2 a3 = __half22float2(*(__half2*)&r3.x), b3 = __half22float2(*(__half2*)&r3.y);
        ax += (a0.x + a1.x) + (a2.x + a3.x);
        ay += (a0.y + a1.y) + (a2.y + a3.y);
        az += (b0.x + b1.x) + (b2.x + b3.x);
        aw += (b0.y + b1.y) + (b2.y + b3.y);
    }
    for (; t < e; t++) {
        int s = g_col[t];
        uint2 r = *(const uint2*)&g_h2[(size_t)s * HH + lane * 4];
        float2 a = __half22float2(*(__half2*)&r.x);
        float2 bq = __half22float2(*(__half2*)&r.y);
        ax += a.x; ay += a.y; az += bq.x; aw += bq.y;
    }
    int c0 = lane * 4;
    float4 bb = *(const float4*)&c1b[c0];
    float4 dd = *(const float4*)&du[(size_t)node * DD + c0];
    float o[4] = {di * ax + bb.x, di * ay + bb.y, di * az + bb.z, di * aw + bb.w};
    float d4[4] = {dd.x, dd.y, dd.z, dd.w};
#pragma unroll
    for (int q = 0; q < 4; q++) {
        float val = (d4[q] >= 0.5f) ? o[q] * 2.f : 0.f;
        o[q] = fmaxf(val, 0.f);
    }
    uint2 pk;
    __half2 h0 = __floats2half2_rn(o[0], o[1]);
    __half2 h1 = __floats2half2_rn(o[2], o[3]);
    pk.x = *(unsigned*)&h0;
    pk.y = *(unsigned*)&h1;
    *(uint2*)&g_h3[base] = pk;
}

// ---------------- aggregation 2 (fp16, 64 feats) + bias + fused mean-pool ----
#define NPW 8
__global__ void k_agg2(const float* __restrict__ c2b) {
    int w = (blockIdx.x * blockDim.x + threadIdx.x) >> 5;
    int lane = threadIdx.x & 31;
    int n0 = w * NPW;
    if (n0 >= NN) return;
    int n1 = min(n0 + NPW, NN);
    int c0 = lane * 2;
    float b0 = c2b[c0], b1 = c2b[c0 + 1];
    int curg = -1;
    float s0 = 0.f, s1 = 0.f;
    for (int node = n0; node < n1; node++) {
        float di = g_dis[node];
        float2 v = __half22float2(*(const __half2*)&g_h4[(size_t)node * HO + c0]);
        float a0 = v.x, a1 = v.y;
        int b = g_rowptr[node];
        int e = b + g_deg[node];
        int t = b;
        for (; t + 8 <= e; t += 8) {
            int si[8];
#pragma unroll
            for (int q = 0; q < 8; q++) si[q] = g_col[t + q];
            float2 u[8];
#pragma unroll
            for (int q = 0; q < 8; q++)
                u[q] = __half22float2(*(const __half2*)&g_h4[(size_t)si[q] * HO + c0]);
#pragma unroll
            for (int q = 0; q < 8; q++) { a0 += u[q].x; a1 += u[q].y; }
        }
        for (; t + 4 <= e; t += 4) {
            int x0 = g_col[t], x1 = g_col[t + 1], x2 = g_col[t + 2], x3 = g_col[t + 3];
            float2 u0 = __half22float2(*(const __half2*)&g_h4[(size_t)x0 * HO + c0]);
            float2 u1 = __half22float2(*(const __half2*)&g_h4[(size_t)x1 * HO + c0]);
            float2 u2 = __half22float2(*(const __half2*)&g_h4[(size_t)x2 * HO + c0]);
            float2 u3 = __half22float2(*(const __half2*)&g_h4[(size_t)x3 * HO + c0]);
            a0 += (u0.x + u1.x) + (u2.x + u3.x);
            a1 += (u0.y + u1.y) + (u2.y + u3.y);
        }
        for (; t < e; t++) {
            int s = g_col[t];
            float2 u = __half22float2(*(const __half2*)&g_h4[(size_t)s * HO + c0]);
            a0 += u.x; a1 += u.y;
        }
        float v0 = di * a0 + b0;
        float v1 = di * a1 + b1;
        int g = g_batch[node];
        if (g != curg) {
            if (curg >= 0) {
                atomicAdd(&g_pool[curg * HO + c0], s0);
                atomicAdd(&g_pool[curg * HO + c0 + 1], s1);
            }
            curg = g;
            s0 = 0.f; s1 = 0.f;
        }
        s0 += v0; s1 += v1;
    }
    if (curg >= 0) {
        atomicAdd(&g_pool[curg * HO + c0], s0);
        atomicAdd(&g_pool[curg * HO + c0 + 1], s1);
    }
}

// ---------------- final: (pool / cnt) @ lin2_w + lin2_b + restore invariants
__device__ __forceinline__ int d_lower_bound(int g) {
    int lo = 0, hi = NN;
    while (lo < hi) {
        int m = (lo + hi) >> 1;
        if (g_batch[m] < g) lo = m + 1; else hi = m;
    }
    return lo;
}

__global__ void k_final(const float* __restrict__ w2, const float* __restrict__ b2,
                        float* __restrict__ out) {
    int idx = blockIdx.x * blockDim.x + threadIdx.x;
    int st = gridDim.x * blockDim.x;
    // restore invariants for the next call (statics start zeroed)
    for (int j = idx; j < NN; j += st) g_deg[j] = 0;
    if (idx == 0) g_base_ctr = 0;
    if (idx < NG * NCLS) {
        int g = idx / NCLS, c = idx % NCLS;
        int cnt = d_lower_bound(g + 1) - d_lower_bound(g);
        float cf = (float)cnt;
        if (cf < 1.f) cf = 1.f;
        float inv = 1.f / cf;
        float s = 0.f;
        for (int j = 0; j < HO; j++) s += g_pool[g * HO + j] * inv * w2[j * NCLS + c];
        out[idx] = s + b2[c];
    }
}

// ---------------- host launcher --------------------------------------------
extern "C" void kernel_launch(void* const* d_in, const int* in_sizes, int n_in,
                              void* d_out, int out_size) {
    const float* x = (const float*)d_in[0];
    const void* edge = d_in[1];
    const void* batch = d_in[2];
    int off = (n_in >= 13 && in_sizes[3] == 1) ? 1 : 0;
    const float* drop_u = (const float*)d_in[3 + off];
    const float* l1w = (const float*)d_in[4 + off];
    const float* l1b = (const float*)d_in[5 + off];
    const float* c1w = (const float*)d_in[6 + off];
    const float* c1b = (const float*)d_in[7 + off];
    const float* c2w = (const float*)d_in[8 + off];
    const float* c2b = (const float*)d_in[9 + off];
    const float* l2w = (const float*)d_in[10 + off];
    const float* l2b = (const float*)d_in[11 + off];
    float* out = (float*)d_out;
    long esz = in_sizes[1];
    long bsz = in_sizes[2];

    k_prep<<<2048, 256>>>(edge, esz, batch, bsz);
    {
        int fold_blocks = (FOLD_ITEMS + 1023) / 1024;
        k_scan_fold<<<SCAN_BLOCKS + fold_blocks, 1024>>>(l1w, l1b, c1w, c2w);
    }
    k_fill<<<2048, 256>>>(edge, esz);
    k_gemm1<<<GB1, 256>>>(x);
    k_agg1<<<(NN + 7) / 8, 256>>>(c1b, drop_u);
    k_gemm2<<<GB1 + 1, 256>>>();
    {
        int warps = (NN + NPW - 1) / NPW;
        int blocks = (warps + 7) / 8;
        k_agg2<<<blocks, 256>>>(c2b);
    }
    k_final<<<512, 256>>>(l2w, l2b, out);
    (void)out_size;
}

// round 13
// speedup vs baseline: 1.4916x; 1.4916x over previous
#include <cuda_runtime.h>
#include <cuda_fp16.h>
#include <math.h>

#define NN 100000
#define NE 1600000
#define DD 128
#define HH 128
#define HO 64
#define NCLS 10
#define NG 128

// ---------------- device scratch (static, zero-init; no runtime alloc) ------
// INVARIANTS (hold at entry of every call; statics start zeroed, and every
// call re-establishes them): g_deg == 0 (re-zeroed in k_final),
// g_base_ctr == 0 (reset in k_final). g_pool is zeroed inside k_gemm2.
__device__ int    g_col[NE];
__device__ int    g_rank[NE];             // rank of edge within its dst segment
__device__ int    g_batch[NN];
__device__ int    g_deg[NN];
__device__ float  g_dis[NN];
__device__ int    g_rowptr[NN];
__device__ int    g_base_ctr;
__device__ __half g_W12T[HH * DD];        // (lin1_w @ conv1_w)^T, fp16 n-major
__device__ float  g_b12[HH];
__device__ __half g_W2T[HO * DD];         // conv2_w^T, fp16 n-major
__device__ __half g_h2[(size_t)NN * HH];  // (x@W12 + b12) * dis[row]  (fp16)
__device__ __half g_h3[(size_t)NN * HH];  // after agg1 + bias + dropout + relu (fp16)
__device__ __half g_h4[(size_t)NN * HO];  // (h3@conv2_w) * dis[row]   (fp16)
__device__ float  g_pool[NG * HO];

// ---------------- dtype detection (per-block, cheap: 64 sampled loads) ------
__device__ __forceinline__ int detect_e64(const unsigned int* __restrict__ ew, long esz) {
    int f = 0;
#pragma unroll 8
    for (int i = 0; i < 64; i++) {
        long idx = 1 + 2 * ((long)i * ((esz - 2) / 2) / 64);
        if (idx >= esz) idx = esz - 1;
        if (!(idx & 1)) idx--;
        if (idx >= 0 && idx < esz && ew[idx] != 0u) f = 1;
    }
    return !f;
}
__device__ __forceinline__ int detect_b64(const unsigned int* __restrict__ bw, long bsz) {
    int f = 0;
#pragma unroll 8
    for (int i = 0; i < 64; i++) {
        long j = bsz / 2 + ((long)i * (bsz / 2) / 64);
        if (!(j & 1)) j++;
        if (j < bsz && bw[j] != 0u) f = 1;
    }
    return !f;
}

// ---------------- warp mma / ldmatrix helpers -------------------------------
__device__ __forceinline__ void mma16816(float* c, const unsigned* a, const unsigned* b) {
    asm volatile(
        "mma.sync.aligned.m16n8k16.row.col.f32.f16.f16.f32 "
        "{%0,%1,%2,%3}, {%4,%5,%6,%7}, {%8,%9}, {%0,%1,%2,%3};"
        : "+f"(c[0]), "+f"(c[1]), "+f"(c[2]), "+f"(c[3])
        : "r"(a[0]), "r"(a[1]), "r"(a[2]), "r"(a[3]), "r"(b[0]), "r"(b[1]));
}
__device__ __forceinline__ void ldsm_x4(unsigned* r, const void* p) {
    unsigned addr = (unsigned)__cvta_generic_to_shared(p);
    asm volatile("ldmatrix.sync.aligned.m8n8.x4.shared.b16 {%0,%1,%2,%3}, [%4];"
                 : "=r"(r[0]), "=r"(r[1]), "=r"(r[2]), "=r"(r[3]) : "r"(addr));
}
__device__ __forceinline__ void ldsm_x2(unsigned* r, const void* p) {
    unsigned addr = (unsigned)__cvta_generic_to_shared(p);
    asm volatile("ldmatrix.sync.aligned.m8n8.x2.shared.b16 {%0,%1}, [%2];"
                 : "=r"(r[0]), "=r"(r[1]) : "r"(addr));
}

// ---------------- degree histogram (returns rank!) + batch convert ----------
__global__ void k_prep(const void* __restrict__ ep, long esz,
                       const void* __restrict__ bp, long bsz) {
    int e64 = detect_e64((const unsigned int*)ep, esz);
    int b64 = detect_b64((const unsigned int*)bp, bsz);
    long stride = (long)gridDim.x * blockDim.x;
    long i0 = (long)blockIdx.x * blockDim.x + threadIdx.x;
    if (e64) {
        const long long* p = (const long long*)ep;
        for (long i = i0; i < NE; i += stride)
            g_rank[i] = atomicAdd(&g_deg[(int)p[NE + i]], 1);
    } else {
        const int* p = (const int*)ep;
        for (long i = i0; i < NE; i += stride)
            g_rank[i] = atomicAdd(&g_deg[p[NE + i]], 1);
    }
    if (b64) {
        const long long* p = (const long long*)bp;
        for (long i = i0; i < NN; i += stride) g_batch[i] = (int)p[i];
    } else {
        const int* p = (const int*)bp;
        for (long i = i0; i < NN; i += stride) g_batch[i] = p[i];
    }
}

// ---------------- merged: unordered scan (blocks < SB) + weight fold --------
#define SCAN_BLOCKS 98
#define FOLD_ITEMS (DD * HH + HH + HH * HO)
__global__ void k_scan_fold(const float* __restrict__ l1w, const float* __restrict__ l1b,
                            const float* __restrict__ c1w, const float* __restrict__ c2w) {
    if (blockIdx.x < SCAN_BLOCKS) {
        __shared__ int s[1024];
        __shared__ int sbase;
        int t = threadIdx.x;
        int i = blockIdx.x * 1024 + t;
        int v = (i < NN) ? g_deg[i] : 0;
        s[t] = v;
        __syncthreads();
        for (int o = 1; o < 1024; o <<= 1) {
            int add = (t >= o) ? s[t - o] : 0;
            __syncthreads();
            if (t >= o) s[t] += add;
            __syncthreads();
        }
        if (t == 1023) sbase = atomicAdd(&g_base_ctr, s[1023]);
        __syncthreads();
        if (i < NN) {
            g_rowptr[i] = s[t] - v + sbase;
            g_dis[i] = rsqrtf((float)(v + 1));  // +1 for the self loop
        }
    } else {
        int idx = (blockIdx.x - SCAN_BLOCKS) * 1024 + threadIdx.x;
        if (idx < DD * HH) {
            int k = idx / HH, m = idx % HH;
            float s = 0.f;
            for (int j = 0; j < DD; j++) s += l1w[k * DD + j] * c1w[j * HH + m];
            g_W12T[m * DD + k] = __float2half(s);
        } else if (idx < DD * HH + HH) {
            int m = idx - DD * HH;
            float s = 0.f;
            for (int j = 0; j < DD; j++) s += l1b[j] * c1w[j * HH + m];
            g_b12[m] = s;
        } else if (idx < FOLD_ITEMS) {
            int j = idx - (DD * HH + HH);
            int k = j / HO, n = j % HO;
            g_W2T[n * DD + k] = __float2half(c2w[k * HO + n]);
        }
    }
}

// ---------------- CSR fill (atomic-free, separate kernel: low regs, full occ)
__global__ void k_fill(const void* __restrict__ ep, long esz) {
    int e64 = detect_e64((const unsigned int*)ep, esz);
    long stride = (long)gridDim.x * blockDim.x;
    long i0 = (long)blockIdx.x * blockDim.x + threadIdx.x;
    if (e64) {
        const long long* p = (const long long*)ep;
        for (long i = i0; i < NE; i += stride) {
            int s = (int)p[i];
            int d = (int)p[NE + i];
            g_col[g_rowptr[d] + g_rank[i]] = s;
        }
    } else {
        const int* p = (const int*)ep;
        for (long i = i0; i < NE; i += stride) {
            int s = p[i];
            int d = p[NE + i];
            g_col[g_rowptr[d] + g_rank[i]] = s;
        }
    }
}

// ---------------- HMMA GEMM body (ldmatrix fragment loads) -------------------
// out[n][MOUT] = (A[n][128] @ W (+bias)) * dis[n]
// MODE 1: A = x (fp32), W = g_W12T, bias = g_b12, out = g_h2
// MODE 2: A = g_h3 (fp16), W = g_W2T, no bias,    out = g_h4
template <int MOUT, int MODE>
__device__ __forceinline__ void gemm_body(const float* __restrict__ x, int row0) {
    constexpr int ROWS = 64;
    constexpr int KPAD = 72;                 // 144B row stride -> LDSM conflict-free
    constexpr int NW = MOUT / 4;             // warp n-width (32 or 16)
    constexpr int NT = NW / 8;               // n8-tiles per warp (4 or 2)
    __shared__ __half As[ROWS][KPAD];
    __shared__ __half Ws[MOUT][KPAD];

    int tid = threadIdx.x;
    int wid = tid >> 5, lane = tid & 31;
    int gid = lane >> 2, tg = lane & 3;
    int wm = wid >> 2, wn = wid & 3;         // 2 x 4 warp grid
    __half* out = (MODE == 1) ? g_h2 : g_h4;
    const __half* WT = (MODE == 1) ? g_W12T : g_W2T;

    // ldmatrix lane-address components
    int a_row = (lane & 15);                 // rows r0..r0+15
    int a_col8 = (lane >> 4) << 3;           // cols kk+0 / kk+8
    int b_row = (lane & 7);                  // rows n0..n0+7
    int b_col8 = ((lane >> 3) & 1) << 3;     // cols kk+0 / kk+8 (lanes 0-15 used)

    float acc[2][NT][4];
#pragma unroll
    for (int mt = 0; mt < 2; mt++)
#pragma unroll
        for (int nt = 0; nt < NT; nt++)
#pragma unroll
            for (int q = 0; q < 4; q++) acc[mt][nt][q] = 0.f;

#pragma unroll
    for (int ch = 0; ch < 2; ch++) {
        int k0 = ch * 64;
        if (MODE == 1) {
#pragma unroll
            for (int idx = tid; idx < ROWS * 16; idx += 256) {
                int r = idx >> 4, q = idx & 15;
                int gr = row0 + r;
                float4 v = make_float4(0.f, 0.f, 0.f, 0.f);
                if (gr < NN) v = *(const float4*)&x[(size_t)gr * DD + k0 + q * 4];
                *(__half2*)&As[r][q * 4]     = __floats2half2_rn(v.x, v.y);
                *(__half2*)&As[r][q * 4 + 2] = __floats2half2_rn(v.z, v.w);
            }
        } else {
#pragma unroll
            for (int idx = tid; idx < ROWS * 8; idx += 256) {
                int r = idx >> 3, q = idx & 7;
                int gr = row0 + r;
                uint4 v = make_uint4(0u, 0u, 0u, 0u);
                if (gr < NN) v = *(const uint4*)&g_h3[(size_t)gr * HH + k0 + q * 8];
                *(uint4*)&As[r][q * 8] = v;
            }
        }
#pragma unroll
        for (int idx = tid; idx < MOUT * 8; idx += 256) {
            int n = idx >> 3, q = idx & 7;
            *(uint4*)&Ws[n][q * 8] = *(const uint4*)&WT[n * DD + k0 + q * 8];
        }
        __syncthreads();
#pragma unroll
        for (int ks = 0; ks < 4; ks++) {
            int kk = ks * 16;
            unsigned af[2][4];
#pragma unroll
            for (int mt = 0; mt < 2; mt++)
                ldsm_x4(af[mt], &As[wm * 32 + mt * 16 + a_row][kk + a_col8]);
            unsigned bf[NT][2];
#pragma unroll
            for (int nt = 0; nt < NT; nt++)
                ldsm_x2(bf[nt], &Ws[wn * NW + nt * 8 + b_row][kk + b_col8]);
#pragma unroll
            for (int mt = 0; mt < 2; mt++)
#pragma unroll
                for (int nt = 0; nt < NT; nt++)
                    mma16816(acc[mt][nt], af[mt], bf[nt]);
        }
        __syncthreads();
    }

#pragma unroll
    for (int mt = 0; mt < 2; mt++) {
        int r_lo = row0 + wm * 32 + mt * 16 + gid;
        int r_hi = r_lo + 8;
        float dlo = (r_lo < NN) ? g_dis[r_lo] : 0.f;
        float dhi = (r_hi < NN) ? g_dis[r_hi] : 0.f;
#pragma unroll
        for (int nt = 0; nt < NT; nt++) {
            int n = wn * NW + nt * 8 + tg * 2;
            float b0 = 0.f, b1 = 0.f;
            if (MODE == 1) { b0 = g_b12[n]; b1 = g_b12[n + 1]; }
            if (r_lo < NN)
                *(__half2*)&out[(size_t)r_lo * MOUT + n] =
                    __floats2half2_rn((acc[mt][nt][0] + b0) * dlo,
                                      (acc[mt][nt][1] + b1) * dlo);
            if (r_hi < NN)
                *(__half2*)&out[(size_t)r_hi * MOUT + n] =
                    __floats2half2_rn((acc[mt][nt][2] + b0) * dhi,
                                      (acc[mt][nt][3] + b1) * dhi);
        }
    }
}

#define GB1 ((NN + 63) / 64)

// ---------------- GEMM1 (separate kernel, full tensor occupancy) ------------
__global__ void __launch_bounds__(256) k_gemm1(const float* __restrict__ x) {
    gemm_body<HH, 1>(x, blockIdx.x * 64);
}

// ---------------- GEMM2 + pool zeroing (one extra trivial block) ------------
__global__ void __launch_bounds__(256) k_gemm2(void) {
    if (blockIdx.x < GB1) {
        gemm_body<HO, 2>(nullptr, blockIdx.x * 64);
    } else {
        for (int j = threadIdx.x; j < NG * HO; j += 256) g_pool[j] = 0.f;
    }
}

// ---------------- aggregation 1 (gather-sum fp16, 128 feats) + bias/drop/relu
__global__ void k_agg1(const float* __restrict__ c1b, const float* __restrict__ du) {
    int node = (blockIdx.x * blockDim.x + threadIdx.x) >> 5;
    int lane = threadIdx.x & 31;
    if (node >= NN) return;
    float di = g_dis[node];
    size_t base = (size_t)node * HH + lane * 4;
    uint2 rs = *(const uint2*)&g_h2[base];  // self loop term
    float2 f0 = __half22float2(*(__half2*)&rs.x);
    float2 f1 = __half22float2(*(__half2*)&rs.y);
    float ax = f0.x, ay = f0.y, az = f1.x, aw = f1.y;
    int b = g_rowptr[node];
    int e = b + g_deg[node];
    int t = b;
    for (; t + 8 <= e; t += 8) {
        int si[8];
#pragma unroll
        for (int q = 0; q < 8; q++) si[q] = g_col[t + q];
        uint2 r[8];
#pragma unroll
        for (int q = 0; q < 8; q++)
            r[q] = *(const uint2*)&g_h2[(size_t)si[q] * HH + lane * 4];
#pragma unroll
        for (int q = 0; q < 8; q++) {
            float2 a = __half22float2(*(__half2*)&r[q].x);
            float2 bb = __half22float2(*(__half2*)&r[q].y);
            ax += a.x; ay += a.y; az += bb.x; aw += bb.y;
        }
    }
    for (; t + 4 <= e; t += 4) {
        int s0 = g_col[t], s1 = g_col[t + 1], s2 = g_col[t + 2], s3 = g_col[t + 3];
        uint2 r0 = *(const uint2*)&g_h2[(size_t)s0 * HH + lane * 4];
        uint2 r1 = *(const uint2*)&g_h2[(size_t)s1 * HH + lane * 4];
        uint2 r2 = *(const uint2*)&g_h2[(size_t)s2 * HH + lane * 4];
        uint2 r3 = *(const uint2*)&g_h2[(size_t)s3 * HH + lane * 4];
        float2 a0 = __half22float2(*(__half2*)&r0.x), b0 = __half22float2(*(__half2*)&r0.y);
        float2 a1 = __half22float2(*(__half2*)&r1.x), b1 = __half22float2(*(__half2*)&r1.y);
        float2 a2 = __half22float2(*(__half2*)&r2.x), b2 = __half22float2(*(__half2*)&r2.y);
        float2 a3 = __half22float2(*(__half2*)&r3.x), b3 = __half22float2(*(__half2*)&r3.y);
        ax += (a0.x + a1.x) + (a2.x + a3.x);
        ay += (a0.y + a1.y) + (a2.y + a3.y);
        az += (b0.x + b1.x) + (b2.x + b3.x);
        aw += (b0.y + b1.y) + (b2.y + b3.y);
    }
    for (; t < e; t++) {
        int s = g_col[t];
        uint2 r = *(const uint2*)&g_h2[(size_t)s * HH + lane * 4];
        float2 a = __half22float2(*(__half2*)&r.x);
        float2 bq = __half22float2(*(__half2*)&r.y);
        ax += a.x; ay += a.y; az += bq.x; aw += bq.y;
    }
    int c0 = lane * 4;
    float4 bb = *(const float4*)&c1b[c0];
    float4 dd = *(const float4*)&du[(size_t)node * DD + c0];
    float o[4] = {di * ax + bb.x, di * ay + bb.y, di * az + bb.z, di * aw + bb.w};
    float d4[4] = {dd.x, dd.y, dd.z, dd.w};
#pragma unroll
    for (int q = 0; q < 4; q++) {
        float val = (d4[q] >= 0.5f) ? o[q] * 2.f : 0.f;
        o[q] = fmaxf(val, 0.f);
    }
    uint2 pk;
    __half2 h0 = __floats2half2_rn(o[0], o[1]);
    __half2 h1 = __floats2half2_rn(o[2], o[3]);
    pk.x = *(unsigned*)&h0;
    pk.y = *(unsigned*)&h1;
    *(uint2*)&g_h3[base] = pk;
}

// ---------------- aggregation 2 (fp16, 64 feats) + bias + fused mean-pool ----
#define NPW 8
__global__ void k_agg2(const float* __restrict__ c2b) {
    int w = (blockIdx.x * blockDim.x + threadIdx.x) >> 5;
    int lane = threadIdx.x & 31;
    int n0 = w * NPW;
    if (n0 >= NN) return;
    int n1 = min(n0 + NPW, NN);
    int c0 = lane * 2;
    float b0 = c2b[c0], b1 = c2b[c0 + 1];
    int curg = -1;
    float s0 = 0.f, s1 = 0.f;
    for (int node = n0; node < n1; node++) {
        float di = g_dis[node];
        float2 v = __half22float2(*(const __half2*)&g_h4[(size_t)node * HO + c0]);
        float a0 = v.x, a1 = v.y;
        int b = g_rowptr[node];
        int e = b + g_deg[node];
        int t = b;
        for (; t + 8 <= e; t += 8) {
            int si[8];
#pragma unroll
            for (int q = 0; q < 8; q++) si[q] = g_col[t + q];
            float2 u[8];
#pragma unroll
            for (int q = 0; q < 8; q++)
                u[q] = __half22float2(*(const __half2*)&g_h4[(size_t)si[q] * HO + c0]);
#pragma unroll
            for (int q = 0; q < 8; q++) { a0 += u[q].x; a1 += u[q].y; }
        }
        for (; t + 4 <= e; t += 4) {
            int x0 = g_col[t], x1 = g_col[t + 1], x2 = g_col[t + 2], x3 = g_col[t + 3];
            float2 u0 = __half22float2(*(const __half2*)&g_h4[(size_t)x0 * HO + c0]);
            float2 u1 = __half22float2(*(const __half2*)&g_h4[(size_t)x1 * HO + c0]);
            float2 u2 = __half22float2(*(const __half2*)&g_h4[(size_t)x2 * HO + c0]);
            float2 u3 = __half22float2(*(const __half2*)&g_h4[(size_t)x3 * HO + c0]);
            a0 += (u0.x + u1.x) + (u2.x + u3.x);
            a1 += (u0.y + u1.y) + (u2.y + u3.y);
        }
        for (; t < e; t++) {
            int s = g_col[t];
            float2 u = __half22float2(*(const __half2*)&g_h4[(size_t)s * HO + c0]);
            a0 += u.x; a1 += u.y;
        }
        float v0 = di * a0 + b0;
        float v1 = di * a1 + b1;
        int g = g_batch[node];
        if (g != curg) {
            if (curg >= 0) {
                atomicAdd(&g_pool[curg * HO + c0], s0);
                atomicAdd(&g_pool[curg * HO + c0 + 1], s1);
            }
            curg = g;
            s0 = 0.f; s1 = 0.f;
        }
        s0 += v0; s1 += v1;
    }
    if (curg >= 0) {
        atomicAdd(&g_pool[curg * HO + c0], s0);
        atomicAdd(&g_pool[curg * HO + c0 + 1], s1);
    }
}

// ---------------- final: (pool / cnt) @ lin2_w + lin2_b + restore invariants
__device__ __forceinline__ int d_lower_bound(int g) {
    int lo = 0, hi = NN;
    while (lo < hi) {
        int m = (lo + hi) >> 1;
        if (g_batch[m] < g) lo = m + 1; else hi = m;
    }
    return lo;
}

__global__ void k_final(const float* __restrict__ w2, const float* __restrict__ b2,
                        float* __restrict__ out) {
    int idx = blockIdx.x * blockDim.x + threadIdx.x;
    int st = gridDim.x * blockDim.x;
    // restore invariants for the next call (statics start zeroed)
    for (int j = idx; j < NN; j += st) g_deg[j] = 0;
    if (idx == 0) g_base_ctr = 0;
    if (idx < NG * NCLS) {
        int g = idx / NCLS, c = idx % NCLS;
        int cnt = d_lower_bound(g + 1) - d_lower_bound(g);
        float cf = (float)cnt;
        if (cf < 1.f) cf = 1.f;
        float inv = 1.f / cf;
        float s = 0.f;
        for (int j = 0; j < HO; j++) s += g_pool[g * HO + j] * inv * w2[j * NCLS + c];
        out[idx] = s + b2[c];
    }
}

// ---------------- host launcher --------------------------------------------
extern "C" void kernel_launch(void* const* d_in, const int* in_sizes, int n_in,
                              void* d_out, int out_size) {
    const float* x = (const float*)d_in[0];
    const void* edge = d_in[1];
    const void* batch = d_in[2];
    int off = (n_in >= 13 && in_sizes[3] == 1) ? 1 : 0;
    const float* drop_u = (const float*)d_in[3 + off];
    const float* l1w = (const float*)d_in[4 + off];
    const float* l1b = (const float*)d_in[5 + off];
    const float* c1w = (const float*)d_in[6 + off];
    const float* c1b = (const float*)d_in[7 + off];
    const float* c2w = (const float*)d_in[8 + off];
    const float* c2b = (const float*)d_in[9 + off];
    const float* l2w = (const float*)d_in[10 + off];
    const float* l2b = (const float*)d_in[11 + off];
    float* out = (float*)d_out;
    long esz = in_sizes[1];
    long bsz = in_sizes[2];

    k_prep<<<2048, 256>>>(edge, esz, batch, bsz);
    {
        int fold_blocks = (FOLD_ITEMS + 1023) / 1024;
        k_scan_fold<<<SCAN_BLOCKS + fold_blocks, 1024>>>(l1w, l1b, c1w, c2w);
    }
    k_fill<<<2048, 256>>>(edge, esz);
    k_gemm1<<<GB1, 256>>>(x);
    k_agg1<<<(NN + 7) / 8, 256>>>(c1b, drop_u);
    k_gemm2<<<GB1 + 1, 256>>>();
    {
        int warps = (NN + NPW - 1) / NPW;
        int blocks = (warps + 7) / 8;
        k_agg2<<<blocks, 256>>>(c2b);
    }
    k_final<<<512, 256>>>(l2w, l2b, out);
    (void)out_size;
}

// round 14
// speedup vs baseline: 1.5548x; 1.0424x over previous
#include <cuda_runtime.h>
#include <cuda_fp16.h>
#include <math.h>

#define NN 100000
#define NE 1600000
#define DD 128
#define HH 128
#define HO 64
#define NCLS 10
#define NG 128

// ---------------- device scratch (static, zero-init; no runtime alloc) ------
// INVARIANTS (hold at entry of every call; statics start zeroed, and every
// call re-establishes them): g_deg == 0 (re-zeroed in k_final),
// g_base_ctr == 0 (reset in k_final). g_pool is zeroed inside k_gemm2.
__device__ int    g_col[NE];
__device__ int    g_rank[NE];             // rank of edge within its dst segment
__device__ int    g_batch[NN];
__device__ int    g_deg[NN];
__device__ float  g_dis[NN];
__device__ int    g_rowptr[NN];
__device__ int    g_base_ctr;
__device__ __half g_W12T[HH * DD];        // (lin1_w @ conv1_w)^T, fp16 n-major
__device__ float  g_b12[HH];
__device__ __half g_W2T[HO * DD];         // conv2_w^T, fp16 n-major
__device__ __half g_h2[(size_t)NN * HH];  // (x@W12 + b12) * dis[row]  (fp16)
__device__ __half g_h3[(size_t)NN * HH];  // after agg1 + bias + dropout + relu (fp16)
__device__ __half g_h4[(size_t)NN * HO];  // (h3@conv2_w) * dis[row]   (fp16)
__device__ float  g_pool[NG * HO];

// ---------------- dtype detection (per-block, cheap: 64 sampled loads) ------
__device__ __forceinline__ int detect_e64(const unsigned int* __restrict__ ew, long esz) {
    int f = 0;
#pragma unroll 8
    for (int i = 0; i < 64; i++) {
        long idx = 1 + 2 * ((long)i * ((esz - 2) / 2) / 64);
        if (idx >= esz) idx = esz - 1;
        if (!(idx & 1)) idx--;
        if (idx >= 0 && idx < esz && ew[idx] != 0u) f = 1;
    }
    return !f;
}
__device__ __forceinline__ int detect_b64(const unsigned int* __restrict__ bw, long bsz) {
    int f = 0;
#pragma unroll 8
    for (int i = 0; i < 64; i++) {
        long j = bsz / 2 + ((long)i * (bsz / 2) / 64);
        if (!(j & 1)) j++;
        if (j < bsz && bw[j] != 0u) f = 1;
    }
    return !f;
}

// ---------------- warp mma / ldmatrix helpers -------------------------------
__device__ __forceinline__ void mma16816(float* c, const unsigned* a, const unsigned* b) {
    asm volatile(
        "mma.sync.aligned.m16n8k16.row.col.f32.f16.f16.f32 "
        "{%0,%1,%2,%3}, {%4,%5,%6,%7}, {%8,%9}, {%0,%1,%2,%3};"
        : "+f"(c[0]), "+f"(c[1]), "+f"(c[2]), "+f"(c[3])
        : "r"(a[0]), "r"(a[1]), "r"(a[2]), "r"(a[3]), "r"(b[0]), "r"(b[1]));
}
__device__ __forceinline__ void ldsm_x4(unsigned* r, const void* p) {
    unsigned addr = (unsigned)__cvta_generic_to_shared(p);
    asm volatile("ldmatrix.sync.aligned.m8n8.x4.shared.b16 {%0,%1,%2,%3}, [%4];"
                 : "=r"(r[0]), "=r"(r[1]), "=r"(r[2]), "=r"(r[3]) : "r"(addr));
}

// ---------------- degree histogram (returns rank!) + batch convert ----------
__global__ void k_prep(const void* __restrict__ ep, long esz,
                       const void* __restrict__ bp, long bsz) {
    int e64 = detect_e64((const unsigned int*)ep, esz);
    int b64 = detect_b64((const unsigned int*)bp, bsz);
    long stride = (long)gridDim.x * blockDim.x;
    long i0 = (long)blockIdx.x * blockDim.x + threadIdx.x;
    if (e64) {
        const long long* p = (const long long*)ep;
        for (long i = i0; i < NE; i += stride)
            g_rank[i] = atomicAdd(&g_deg[(int)p[NE + i]], 1);
    } else {
        const int* p = (const int*)ep;
        for (long i = i0; i < NE; i += stride)
            g_rank[i] = atomicAdd(&g_deg[p[NE + i]], 1);
    }
    if (b64) {
        const long long* p = (const long long*)bp;
        for (long i = i0; i < NN; i += stride) g_batch[i] = (int)p[i];
    } else {
        const int* p = (const int*)bp;
        for (long i = i0; i < NN; i += stride) g_batch[i] = p[i];
    }
}

// ---------------- unordered scan (rowptr by arrival order) -------------------
#define SCAN_BLOCKS 98
__global__ void k_scan(void) {
    __shared__ int s[1024];
    __shared__ int sbase;
    int t = threadIdx.x;
    int i = blockIdx.x * 1024 + t;
    int v = (i < NN) ? g_deg[i] : 0;
    s[t] = v;
    __syncthreads();
    for (int o = 1; o < 1024; o <<= 1) {
        int add = (t >= o) ? s[t - o] : 0;
        __syncthreads();
        if (t >= o) s[t] += add;
        __syncthreads();
    }
    if (t == 1023) sbase = atomicAdd(&g_base_ctr, s[1023]);
    __syncthreads();
    if (i < NN) {
        g_rowptr[i] = s[t] - v + sbase;
        g_dis[i] = rsqrtf((float)(v + 1));  // +1 for the self loop
    }
}

// ---------------- weight fold (independent; runs on side stream) ------------
#define FOLD_ITEMS (DD * HH + HH + HH * HO)
__global__ void k_fold(const float* __restrict__ l1w, const float* __restrict__ l1b,
                       const float* __restrict__ c1w, const float* __restrict__ c2w) {
    int idx = blockIdx.x * blockDim.x + threadIdx.x;
    if (idx < DD * HH) {
        int k = idx / HH, m = idx % HH;
        float s = 0.f;
        for (int j = 0; j < DD; j++) s += l1w[k * DD + j] * c1w[j * HH + m];
        g_W12T[m * DD + k] = __float2half(s);
    } else if (idx < DD * HH + HH) {
        int m = idx - DD * HH;
        float s = 0.f;
        for (int j = 0; j < DD; j++) s += l1b[j] * c1w[j * HH + m];
        g_b12[m] = s;
    } else if (idx < FOLD_ITEMS) {
        int j = idx - (DD * HH + HH);
        int k = j / HO, n = j % HO;
        g_W2T[n * DD + k] = __float2half(c2w[k * HO + n]);
    }
}

// ---------------- CSR fill (atomic-free; overlaps gemm1 on side stream) -----
__global__ void k_fill(const void* __restrict__ ep, long esz) {
    int e64 = detect_e64((const unsigned int*)ep, esz);
    long stride = (long)gridDim.x * blockDim.x;
    long i0 = (long)blockIdx.x * blockDim.x + threadIdx.x;
    if (e64) {
        const long long* p = (const long long*)ep;
        for (long i = i0; i < NE; i += stride) {
            int s = (int)p[i];
            int d = (int)p[NE + i];
            g_col[g_rowptr[d] + g_rank[i]] = s;
        }
    } else {
        const int* p = (const int*)ep;
        for (long i = i0; i < NE; i += stride) {
            int s = p[i];
            int d = p[NE + i];
            g_col[g_rowptr[d] + g_rank[i]] = s;
        }
    }
}

// ---------------- HMMA GEMM body (ldmatrix fragment loads) -------------------
// out[n][MOUT] = (A[n][128] @ W (+bias)) * dis[n]
// MODE 1: A = x (fp32), W = g_W12T, bias = g_b12, out = g_h2
// MODE 2: A = g_h3 (fp16), W = g_W2T, no bias,    out = g_h4
template <int MOUT, int MODE>
__device__ __forceinline__ void gemm_body(const float* __restrict__ x, int row0) {
    constexpr int ROWS = 64;
    constexpr int KPAD = 72;                 // 144B row stride -> LDSM conflict-free
    constexpr int NW = MOUT / 4;             // warp n-width (32 or 16)
    constexpr int NT = NW / 8;               // n8-tiles per warp (4 or 2), even
    __shared__ __half As[ROWS][KPAD];
    __shared__ __half Ws[MOUT][KPAD];

    int tid = threadIdx.x;
    int wid = tid >> 5, lane = tid & 31;
    int gid = lane >> 2, tg = lane & 3;
    int wm = wid >> 2, wn = wid & 3;         // 2 x 4 warp grid
    __half* out = (MODE == 1) ? g_h2 : g_h4;
    const __half* WT = (MODE == 1) ? g_W12T : g_W2T;

    // ldmatrix lane-address components
    int a_row = (lane & 15);                 // A x4: rows r0..r0+15, cols kk / kk+8
    int a_col8 = (lane >> 4) << 3;
    int b4_row = (lane & 7) + (((lane >> 4) & 1) << 3);  // B x4: two n8 tiles
    int b4_col = ((lane >> 3) & 1) << 3;

    float acc[2][NT][4];
#pragma unroll
    for (int mt = 0; mt < 2; mt++)
#pragma unroll
        for (int nt = 0; nt < NT; nt++)
#pragma unroll
            for (int q = 0; q < 4; q++) acc[mt][nt][q] = 0.f;

#pragma unroll
    for (int ch = 0; ch < 2; ch++) {
        int k0 = ch * 64;
        if (MODE == 1) {
#pragma unroll
            for (int idx = tid; idx < ROWS * 16; idx += 256) {
                int r = idx >> 4, q = idx & 15;
                int gr = row0 + r;
                float4 v = make_float4(0.f, 0.f, 0.f, 0.f);
                if (gr < NN) v = *(const float4*)&x[(size_t)gr * DD + k0 + q * 4];
                *(__half2*)&As[r][q * 4]     = __floats2half2_rn(v.x, v.y);
                *(__half2*)&As[r][q * 4 + 2] = __floats2half2_rn(v.z, v.w);
            }
        } else {
#pragma unroll
            for (int idx = tid; idx < ROWS * 8; idx += 256) {
                int r = idx >> 3, q = idx & 7;
                int gr = row0 + r;
                uint4 v = make_uint4(0u, 0u, 0u, 0u);
                if (gr < NN) v = *(const uint4*)&g_h3[(size_t)gr * HH + k0 + q * 8];
                *(uint4*)&As[r][q * 8] = v;
            }
        }
#pragma unroll
        for (int idx = tid; idx < MOUT * 8; idx += 256) {
            int n = idx >> 3, q = idx & 7;
            *(uint4*)&Ws[n][q * 8] = *(const uint4*)&WT[n * DD + k0 + q * 8];
        }
        __syncthreads();
#pragma unroll
        for (int ks = 0; ks < 4; ks++) {
            int kk = ks * 16;
            unsigned af[2][4];
#pragma unroll
            for (int mt = 0; mt < 2; mt++)
                ldsm_x4(af[mt], &As[wm * 32 + mt * 16 + a_row][kk + a_col8]);
            unsigned bf[NT][2];
#pragma unroll
            for (int nt = 0; nt < NT; nt += 2) {
                unsigned r4[4];
                ldsm_x4(r4, &Ws[wn * NW + nt * 8 + b4_row][kk + b4_col]);
                bf[nt][0] = r4[0];     bf[nt][1] = r4[1];
                bf[nt + 1][0] = r4[2]; bf[nt + 1][1] = r4[3];
            }
#pragma unroll
            for (int mt = 0; mt < 2; mt++)
#pragma unroll
                for (int nt = 0; nt < NT; nt++)
                    mma16816(acc[mt][nt], af[mt], bf[nt]);
        }
        __syncthreads();
    }

#pragma unroll
    for (int mt = 0; mt < 2; mt++) {
        int r_lo = row0 + wm * 32 + mt * 16 + gid;
        int r_hi = r_lo + 8;
        float dlo = (r_lo < NN) ? g_dis[r_lo] : 0.f;
        float dhi = (r_hi < NN) ? g_dis[r_hi] : 0.f;
#pragma unroll
        for (int nt = 0; nt < NT; nt++) {
            int n = wn * NW + nt * 8 + tg * 2;
            float b0 = 0.f, b1 = 0.f;
            if (MODE == 1) { b0 = g_b12[n]; b1 = g_b12[n + 1]; }
            if (r_lo < NN)
                *(__half2*)&out[(size_t)r_lo * MOUT + n] =
                    __floats2half2_rn((acc[mt][nt][0] + b0) * dlo,
                                      (acc[mt][nt][1] + b1) * dlo);
            if (r_hi < NN)
                *(__half2*)&out[(size_t)r_hi * MOUT + n] =
                    __floats2half2_rn((acc[mt][nt][2] + b0) * dhi,
                                      (acc[mt][nt][3] + b1) * dhi);
        }
    }
}

#define GB1 ((NN + 63) / 64)

// ---------------- GEMM1 (overlaps k_fill on the other stream) ---------------
__global__ void __launch_bounds__(256) k_gemm1(const float* __restrict__ x) {
    gemm_body<HH, 1>(x, blockIdx.x * 64);
}

// ---------------- GEMM2 + pool zeroing (one extra trivial block) ------------
__global__ void __launch_bounds__(256) k_gemm2(void) {
    if (blockIdx.x < GB1) {
        gemm_body<HO, 2>(nullptr, blockIdx.x * 64);
    } else {
        for (int j = threadIdx.x; j < NG * HO; j += 256) g_pool[j] = 0.f;
    }
}

// ---------------- aggregation 1 (gather-sum fp16, 128 feats) + bias/drop/relu
__global__ void k_agg1(const float* __restrict__ c1b, const float* __restrict__ du) {
    int node = (blockIdx.x * blockDim.x + threadIdx.x) >> 5;
    int lane = threadIdx.x & 31;
    if (node >= NN) return;
    float di = g_dis[node];
    size_t base = (size_t)node * HH + lane * 4;
    uint2 rs = *(const uint2*)&g_h2[base];  // self loop term
    float2 f0 = __half22float2(*(__half2*)&rs.x);
    float2 f1 = __half22float2(*(__half2*)&rs.y);
    float ax = f0.x, ay = f0.y, az = f1.x, aw = f1.y;
    int b = g_rowptr[node];
    int e = b + g_deg[node];
    int t = b;
    for (; t + 8 <= e; t += 8) {
        int si[8];
#pragma unroll
        for (int q = 0; q < 8; q++) si[q] = g_col[t + q];
        uint2 r[8];
#pragma unroll
        for (int q = 0; q < 8; q++)
            r[q] = *(const uint2*)&g_h2[(size_t)si[q] * HH + lane * 4];
#pragma unroll
        for (int q = 0; q < 8; q++) {
            float2 a = __half22float2(*(__half2*)&r[q].x);
            float2 bb = __half22float2(*(__half2*)&r[q].y);
            ax += a.x; ay += a.y; az += bb.x; aw += bb.y;
        }
    }
    for (; t + 4 <= e; t += 4) {
        int s0 = g_col[t], s1 = g_col[t + 1], s2 = g_col[t + 2], s3 = g_col[t + 3];
        uint2 r0 = *(const uint2*)&g_h2[(size_t)s0 * HH + lane * 4];
        uint2 r1 = *(const uint2*)&g_h2[(size_t)s1 * HH + lane * 4];
        uint2 r2 = *(const uint2*)&g_h2[(size_t)s2 * HH + lane * 4];
        uint2 r3 = *(const uint2*)&g_h2[(size_t)s3 * HH + lane * 4];
        float2 a0 = __half22float2(*(__half2*)&r0.x), b0 = __half22float2(*(__half2*)&r0.y);
        float2 a1 = __half22float2(*(__half2*)&r1.x), b1 = __half22float2(*(__half2*)&r1.y);
        float2 a2 = __half22float2(*(__half2*)&r2.x), b2 = __half22float2(*(__half2*)&r2.y);
        float2 a3 = __half22float2(*(__half2*)&r3.x), b3 = __half22float2(*(__half2*)&r3.y);
        ax += (a0.x + a1.x) + (a2.x + a3.x);
        ay += (a0.y + a1.y) + (a2.y + a3.y);
        az += (b0.x + b1.x) + (b2.x + b3.x);
        aw += (b0.y + b1.y) + (b2.y + b3.y);
    }
    for (; t < e; t++) {
        int s = g_col[t];
        uint2 r = *(const uint2*)&g_h2[(size_t)s * HH + lane * 4];
        float2 a = __half22float2(*(__half2*)&r.x);
        float2 bq = __half22float2(*(__half2*)&r.y);
        ax += a.x; ay += a.y; az += bq.x; aw += bq.y;
    }
    int c0 = lane * 4;
    float4 bb = *(const float4*)&c1b[c0];
    float4 dd = *(const float4*)&du[(size_t)node * DD + c0];
    float o[4] = {di * ax + bb.x, di * ay + bb.y, di * az + bb.z, di * aw + bb.w};
    float d4[4] = {dd.x, dd.y, dd.z, dd.w};
#pragma unroll
    for (int q = 0; q < 4; q++) {
        float val = (d4[q] >= 0.5f) ? o[q] * 2.f : 0.f;
        o[q] = fmaxf(val, 0.f);
    }
    uint2 pk;
    __half2 h0 = __floats2half2_rn(o[0], o[1]);
    __half2 h1 = __floats2half2_rn(o[2], o[3]);
    pk.x = *(unsigned*)&h0;
    pk.y = *(unsigned*)&h1;
    *(uint2*)&g_h3[base] = pk;
}

// ---------------- aggregation 2 (fp16, 64 feats) + bias + fused mean-pool ----
#define NPW 8
__global__ void k_agg2(const float* __restrict__ c2b) {
    int w = (blockIdx.x * blockDim.x + threadIdx.x) >> 5;
    int lane = threadIdx.x & 31;
    int n0 = w * NPW;
    if (n0 >= NN) return;
    int n1 = min(n0 + NPW, NN);
    int c0 = lane * 2;
    float b0 = c2b[c0], b1 = c2b[c0 + 1];
    int curg = -1;
    float s0 = 0.f, s1 = 0.f;
    for (int node = n0; node < n1; node++) {
        float di = g_dis[node];
        float2 v = __half22float2(*(const __half2*)&g_h4[(size_t)node * HO + c0]);
        float a0 = v.x, a1 = v.y;
        int b = g_rowptr[node];
        int e = b + g_deg[node];
        int t = b;
        for (; t + 8 <= e; t += 8) {
            int si[8];
#pragma unroll
            for (int q = 0; q < 8; q++) si[q] = g_col[t + q];
            float2 u[8];
#pragma unroll
            for (int q = 0; q < 8; q++)
                u[q] = __half22float2(*(const __half2*)&g_h4[(size_t)si[q] * HO + c0]);
#pragma unroll
            for (int q = 0; q < 8; q++) { a0 += u[q].x; a1 += u[q].y; }
        }
        for (; t + 4 <= e; t += 4) {
            int x0 = g_col[t], x1 = g_col[t + 1], x2 = g_col[t + 2], x3 = g_col[t + 3];
            float2 u0 = __half22float2(*(const __half2*)&g_h4[(size_t)x0 * HO + c0]);
            float2 u1 = __half22float2(*(const __half2*)&g_h4[(size_t)x1 * HO + c0]);
            float2 u2 = __half22float2(*(const __half2*)&g_h4[(size_t)x2 * HO + c0]);
            float2 u3 = __half22float2(*(const __half2*)&g_h4[(size_t)x3 * HO + c0]);
            a0 += (u0.x + u1.x) + (u2.x + u3.x);
            a1 += (u0.y + u1.y) + (u2.y + u3.y);
        }
        for (; t < e; t++) {
            int s = g_col[t];
            float2 u = __half22float2(*(const __half2*)&g_h4[(size_t)s * HO + c0]);
            a0 += u.x; a1 += u.y;
        }
        float v0 = di * a0 + b0;
        float v1 = di * a1 + b1;
        int g = g_batch[node];
        if (g != curg) {
            if (curg >= 0) {
                atomicAdd(&g_pool[curg * HO + c0], s0);
                atomicAdd(&g_pool[curg * HO + c0 + 1], s1);
            }
            curg = g;
            s0 = 0.f; s1 = 0.f;
        }
        s0 += v0; s1 += v1;
    }
    if (curg >= 0) {
        atomicAdd(&g_pool[curg * HO + c0], s0);
        atomicAdd(&g_pool[curg * HO + c0 + 1], s1);
    }
}

// ---------------- final: (pool / cnt) @ lin2_w + lin2_b + restore invariants
__device__ __forceinline__ int d_lower_bound(int g) {
    int lo = 0, hi = NN;
    while (lo < hi) {
        int m = (lo + hi) >> 1;
        if (g_batch[m] < g) lo = m + 1; else hi = m;
    }
    return lo;
}

__global__ void k_final(const float* __restrict__ w2, const float* __restrict__ b2,
                        float* __restrict__ out) {
    int idx = blockIdx.x * blockDim.x + threadIdx.x;
    int st = gridDim.x * blockDim.x;
    // restore invariants for the next call (statics start zeroed)
    for (int j = idx; j < NN; j += st) g_deg[j] = 0;
    if (idx == 0) g_base_ctr = 0;
    if (idx < NG * NCLS) {
        int g = idx / NCLS, c = idx % NCLS;
        int cnt = d_lower_bound(g + 1) - d_lower_bound(g);
        float cf = (float)cnt;
        if (cf < 1.f) cf = 1.f;
        float inv = 1.f / cf;
        float s = 0.f;
        for (int j = 0; j < HO; j++) s += g_pool[g * HO + j] * inv * w2[j * NCLS + c];
        out[idx] = s + b2[c];
    }
}

// ---------------- host launcher (two-stream graph with event edges) ---------
extern "C" void kernel_launch(void* const* d_in, const int* in_sizes, int n_in,
                              void* d_out, int out_size) {
    const float* x = (const float*)d_in[0];
    const void* edge = d_in[1];
    const void* batch = d_in[2];
    int off = (n_in >= 13 && in_sizes[3] == 1) ? 1 : 0;
    const float* drop_u = (const float*)d_in[3 + off];
    const float* l1w = (const float*)d_in[4 + off];
    const float* l1b = (const float*)d_in[5 + off];
    const float* c1w = (const float*)d_in[6 + off];
    const float* c1b = (const float*)d_in[7 + off];
    const float* c2w = (const float*)d_in[8 + off];
    const float* c2b = (const float*)d_in[9 + off];
    const float* l2w = (const float*)d_in[10 + off];
    const float* l2b = (const float*)d_in[11 + off];
    float* out = (float*)d_out;
    long esz = in_sizes[1];
    long bsz = in_sizes[2];

    // Lazily created once (first call = correctness run, outside capture).
    // Same launches issued on every call -> deterministic work.
    static cudaStream_t s1 = nullptr;
    static cudaEvent_t evFork = nullptr, evFold = nullptr, evScan = nullptr,
                       evFill = nullptr;
    if (s1 == nullptr) {
        cudaStreamCreateWithFlags(&s1, cudaStreamNonBlocking);
        cudaEventCreateWithFlags(&evFork, cudaEventDisableTiming);
        cudaEventCreateWithFlags(&evFold, cudaEventDisableTiming);
        cudaEventCreateWithFlags(&evScan, cudaEventDisableTiming);
        cudaEventCreateWithFlags(&evFill, cudaEventDisableTiming);
    }

    // fork: s1 joins the (captured) main stream
    cudaEventRecord(evFork, 0);
    cudaStreamWaitEvent(s1, evFork, 0);

    // s1: weight fold (independent of graph preprocessing)
    k_fold<<<(FOLD_ITEMS + 255) / 256, 256, 0, s1>>>(l1w, l1b, c1w, c2w);
    cudaEventRecord(evFold, s1);

    // main: histogram+rank, then scan
    k_prep<<<2048, 256>>>(edge, esz, batch, bsz);
    k_scan<<<SCAN_BLOCKS, 1024>>>();
    cudaEventRecord(evScan, 0);

    // s1: CSR fill (needs scan) — overlaps gemm1 on main
    cudaStreamWaitEvent(s1, evScan, 0);
    k_fill<<<2048, 256, 0, s1>>>(edge, esz);
    cudaEventRecord(evFill, s1);

    // main: gemm1 (needs fold + scan, NOT fill)
    cudaStreamWaitEvent(0, evFold, 0);
    k_gemm1<<<GB1, 256>>>(x);

    // join fill, then the serial tail
    cudaStreamWaitEvent(0, evFill, 0);
    k_agg1<<<(NN + 7) / 8, 256>>>(c1b, drop_u);
    k_gemm2<<<GB1 + 1, 256>>>();
    {
        int warps = (NN + NPW - 1) / NPW;
        int blocks = (warps + 7) / 8;
        k_agg2<<<blocks, 256>>>(c2b);
    }
    k_final<<<512, 256>>>(l2w, l2b, out);
    (void)out_size;
}

// round 15
// speedup vs baseline: 2.1872x; 1.4067x over previous
#include <cuda_runtime.h>
#include <cuda_fp16.h>
#include <math.h>

#define NN 100000
#define NE 1600000
#define DD 128
#define HH 128
#define HO 64
#define NCLS 10
#define NG 128

// ---------------- device scratch (static, zero-init; no runtime alloc) ------
// INVARIANTS (hold at entry of every call; statics start zeroed, and every
// call re-establishes them): g_deg == 0 (re-zeroed in k_final),
// g_base_ctr == 0 (reset in k_final). g_pool is zeroed inside k_gemm2.
__device__ int    g_col[NE];
__device__ int    g_rank[NE];             // rank of edge within its dst segment
__device__ int    g_batch[NN];
__device__ int    g_deg[NN];
__device__ float  g_dis[NN];
__device__ int    g_rowptr[NN];
__device__ int    g_base_ctr;
__device__ __half g_W12T[HH * DD];        // (lin1_w @ conv1_w)^T, fp16 n-major
__device__ float  g_b12[HH];
__device__ __half g_W2T[HO * DD];         // conv2_w^T, fp16 n-major
__device__ __half g_h2[(size_t)NN * HH];  // (x@W12 + b12) * dis[row]  (fp16)
__device__ __half g_h3[(size_t)NN * HH];  // after agg1 + bias + dropout + relu (fp16)
__device__ __half g_h4[(size_t)NN * HO];  // (h3@conv2_w) * dis[row]   (fp16)
__device__ float  g_pool[NG * HO];

// ---------------- dtype detection (warp-cooperative: 1 load + ballot) -------
// int64 arrays have zero high words at odd int32 positions; int32 node ids /
// sorted upper-half batch ids are essentially never all zero over 32 samples.
__device__ __forceinline__ int detect_e64_w(const unsigned int* __restrict__ ew,
                                            long esz) {
    int lane = threadIdx.x & 31;
    long idx = 1 + 2 * ((long)lane * ((esz - 2) / 2) / 32);
    if (idx >= esz) idx = esz - 1;
    if (!(idx & 1)) idx--;
    unsigned v = (idx >= 0 && idx < esz) ? ew[idx] : 0u;
    unsigned m = __ballot_sync(0xffffffffu, v != 0u);
    return m == 0u;
}
__device__ __forceinline__ int detect_b64_w(const unsigned int* __restrict__ bw,
                                            long bsz) {
    int lane = threadIdx.x & 31;
    long j = bsz / 2 + ((long)lane * (bsz / 2) / 32);
    if (!(j & 1)) j++;
    unsigned v = (j < bsz) ? bw[j] : 0u;
    unsigned m = __ballot_sync(0xffffffffu, v != 0u);
    return m == 0u;
}

// ---------------- warp mma / ldmatrix helpers -------------------------------
__device__ __forceinline__ void mma16816(float* c, const unsigned* a, const unsigned* b) {
    asm volatile(
        "mma.sync.aligned.m16n8k16.row.col.f32.f16.f16.f32 "
        "{%0,%1,%2,%3}, {%4,%5,%6,%7}, {%8,%9}, {%0,%1,%2,%3};"
        : "+f"(c[0]), "+f"(c[1]), "+f"(c[2]), "+f"(c[3])
        : "r"(a[0]), "r"(a[1]), "r"(a[2]), "r"(a[3]), "r"(b[0]), "r"(b[1]));
}
__device__ __forceinline__ void ldsm_x4(unsigned* r, const void* p) {
    unsigned addr = (unsigned)__cvta_generic_to_shared(p);
    asm volatile("ldmatrix.sync.aligned.m8n8.x4.shared.b16 {%0,%1,%2,%3}, [%4];"
                 : "=r"(r[0]), "=r"(r[1]), "=r"(r[2]), "=r"(r[3]) : "r"(addr));
}

// ---------------- degree histogram (returns rank!) + batch convert ----------
__global__ void k_prep(const void* __restrict__ ep, long esz,
                       const void* __restrict__ bp, long bsz) {
    int e64 = detect_e64_w((const unsigned int*)ep, esz);
    int b64 = detect_b64_w((const unsigned int*)bp, bsz);
    long stride = (long)gridDim.x * blockDim.x;
    long i0 = (long)blockIdx.x * blockDim.x + threadIdx.x;
    if (e64) {
        const long long* p = (const long long*)ep;
        for (long i = i0; i < NE; i += stride)
            g_rank[i] = atomicAdd(&g_deg[(int)p[NE + i]], 1);
    } else {
        const int* p = (const int*)ep;
        for (long i = i0; i < NE; i += stride)
            g_rank[i] = atomicAdd(&g_deg[p[NE + i]], 1);
    }
    if (b64) {
        const long long* p = (const long long*)bp;
        for (long i = i0; i < NN; i += stride) g_batch[i] = (int)p[i];
    } else {
        const int* p = (const int*)bp;
        for (long i = i0; i < NN; i += stride) g_batch[i] = p[i];
    }
}

// ---------------- unordered scan (rowptr by arrival order) -------------------
#define SCAN_BLOCKS 98
__global__ void k_scan(void) {
    __shared__ int s[1024];
    __shared__ int sbase;
    int t = threadIdx.x;
    int i = blockIdx.x * 1024 + t;
    int v = (i < NN) ? g_deg[i] : 0;
    s[t] = v;
    __syncthreads();
    for (int o = 1; o < 1024; o <<= 1) {
        int add = (t >= o) ? s[t - o] : 0;
        __syncthreads();
        if (t >= o) s[t] += add;
        __syncthreads();
    }
    if (t == 1023) sbase = atomicAdd(&g_base_ctr, s[1023]);
    __syncthreads();
    if (i < NN) {
        g_rowptr[i] = s[t] - v + sbase;
        g_dis[i] = rsqrtf((float)(v + 1));  // +1 for the self loop
    }
}

// ---------------- weight fold (independent; runs on side stream) ------------
#define FOLD_ITEMS (DD * HH + HH + HH * HO)
__global__ void k_fold(const float* __restrict__ l1w, const float* __restrict__ l1b,
                       const float* __restrict__ c1w, const float* __restrict__ c2w) {
    int idx = blockIdx.x * blockDim.x + threadIdx.x;
    if (idx < DD * HH) {
        int k = idx / HH, m = idx % HH;
        float s = 0.f;
        for (int j = 0; j < DD; j++) s += l1w[k * DD + j] * c1w[j * HH + m];
        g_W12T[m * DD + k] = __float2half(s);
    } else if (idx < DD * HH + HH) {
        int m = idx - DD * HH;
        float s = 0.f;
        for (int j = 0; j < DD; j++) s += l1b[j] * c1w[j * HH + m];
        g_b12[m] = s;
    } else if (idx < FOLD_ITEMS) {
        int j = idx - (DD * HH + HH);
        int k = j / HO, n = j % HO;
        g_W2T[n * DD + k] = __float2half(c2w[k * HO + n]);
    }
}

// ---------------- CSR fill (atomic-free; overlaps gemm1 on side stream) -----
__global__ void k_fill(const void* __restrict__ ep, long esz) {
    int e64 = detect_e64_w((const unsigned int*)ep, esz);
    long stride = (long)gridDim.x * blockDim.x;
    long i0 = (long)blockIdx.x * blockDim.x + threadIdx.x;
    if (e64) {
        const long long* p = (const long long*)ep;
        for (long i = i0; i < NE; i += stride) {
            int s = (int)p[i];
            int d = (int)p[NE + i];
            g_col[g_rowptr[d] + g_rank[i]] = s;
        }
    } else {
        const int* p = (const int*)ep;
        for (long i = i0; i < NE; i += stride) {
            int s = p[i];
            int d = p[NE + i];
            g_col[g_rowptr[d] + g_rank[i]] = s;
        }
    }
}

// ---------------- HMMA GEMM body (ldmatrix fragment loads) -------------------
// out[n][MOUT] = (A[n][128] @ W (+bias)) * dis[n]
// MODE 1: A = x (fp32), W = g_W12T, bias = g_b12, out = g_h2
// MODE 2: A = g_h3 (fp16), W = g_W2T, no bias,    out = g_h4
template <int MOUT, int MODE>
__device__ __forceinline__ void gemm_body(const float* __restrict__ x, int row0) {
    constexpr int ROWS = 64;
    constexpr int KPAD = 72;                 // 144B row stride -> LDSM conflict-free
    constexpr int NW = MOUT / 4;             // warp n-width (32 or 16)
    constexpr int NT = NW / 8;               // n8-tiles per warp (4 or 2), even
    __shared__ __half As[ROWS][KPAD];
    __shared__ __half Ws[MOUT][KPAD];

    int tid = threadIdx.x;
    int wid = tid >> 5, lane = tid & 31;
    int gid = lane >> 2, tg = lane & 3;
    int wm = wid >> 2, wn = wid & 3;         // 2 x 4 warp grid
    __half* out = (MODE == 1) ? g_h2 : g_h4;
    const __half* WT = (MODE == 1) ? g_W12T : g_W2T;

    // ldmatrix lane-address components
    int a_row = (lane & 15);                 // A x4: rows r0..r0+15, cols kk / kk+8
    int a_col8 = (lane >> 4) << 3;
    int b4_row = (lane & 7) + (((lane >> 4) & 1) << 3);  // B x4: two n8 tiles
    int b4_col = ((lane >> 3) & 1) << 3;

    float acc[2][NT][4];
#pragma unroll
    for (int mt = 0; mt < 2; mt++)
#pragma unroll
        for (int nt = 0; nt < NT; nt++)
#pragma unroll
            for (int q = 0; q < 4; q++) acc[mt][nt][q] = 0.f;

#pragma unroll
    for (int ch = 0; ch < 2; ch++) {
        int k0 = ch * 64;
        if (MODE == 1) {
#pragma unroll
            for (int idx = tid; idx < ROWS * 16; idx += 256) {
                int r = idx >> 4, q = idx & 15;
                int gr = row0 + r;
                float4 v = make_float4(0.f, 0.f, 0.f, 0.f);
                if (gr < NN) v = *(const float4*)&x[(size_t)gr * DD + k0 + q * 4];
                *(__half2*)&As[r][q * 4]     = __floats2half2_rn(v.x, v.y);
                *(__half2*)&As[r][q * 4 + 2] = __floats2half2_rn(v.z, v.w);
            }
        } else {
#pragma unroll
            for (int idx = tid; idx < ROWS * 8; idx += 256) {
                int r = idx >> 3, q = idx & 7;
                int gr = row0 + r;
                uint4 v = make_uint4(0u, 0u, 0u, 0u);
                if (gr < NN) v = *(const uint4*)&g_h3[(size_t)gr * HH + k0 + q * 8];
                *(uint4*)&As[r][q * 8] = v;
            }
        }
#pragma unroll
        for (int idx = tid; idx < MOUT * 8; idx += 256) {
            int n = idx >> 3, q = idx & 7;
            *(uint4*)&Ws[n][q * 8] = *(const uint4*)&WT[n * DD + k0 + q * 8];
        }
        __syncthreads();
#pragma unroll
        for (int ks = 0; ks < 4; ks++) {
            int kk = ks * 16;
            unsigned af[2][4];
#pragma unroll
            for (int mt = 0; mt < 2; mt++)
                ldsm_x4(af[mt], &As[wm * 32 + mt * 16 + a_row][kk + a_col8]);
            unsigned bf[NT][2];
#pragma unroll
            for (int nt = 0; nt < NT; nt += 2) {
                unsigned r4[4];
                ldsm_x4(r4, &Ws[wn * NW + nt * 8 + b4_row][kk + b4_col]);
                bf[nt][0] = r4[0];     bf[nt][1] = r4[1];
                bf[nt + 1][0] = r4[2]; bf[nt + 1][1] = r4[3];
            }
#pragma unroll
            for (int mt = 0; mt < 2; mt++)
#pragma unroll
                for (int nt = 0; nt < NT; nt++)
                    mma16816(acc[mt][nt], af[mt], bf[nt]);
        }
        __syncthreads();
    }

#pragma unroll
    for (int mt = 0; mt < 2; mt++) {
        int r_lo = row0 + wm * 32 + mt * 16 + gid;
        int r_hi = r_lo + 8;
        float dlo = (r_lo < NN) ? g_dis[r_lo] : 0.f;
        float dhi = (r_hi < NN) ? g_dis[r_hi] : 0.f;
#pragma unroll
        for (int nt = 0; nt < NT; nt++) {
            int n = wn * NW + nt * 8 + tg * 2;
            float b0 = 0.f, b1 = 0.f;
            if (MODE == 1) { b0 = g_b12[n]; b1 = g_b12[n + 1]; }
            if (r_lo < NN)
                *(__half2*)&out[(size_t)r_lo * MOUT + n] =
                    __floats2half2_rn((acc[mt][nt][0] + b0) * dlo,
                                      (acc[mt][nt][1] + b1) * dlo);
            if (r_hi < NN)
                *(__half2*)&out[(size_t)r_hi * MOUT + n] =
                    __floats2half2_rn((acc[mt][nt][2] + b0) * dhi,
                                      (acc[mt][nt][3] + b1) * dhi);
        }
    }
}

#define GB1 ((NN + 63) / 64)

// ---------------- GEMM1 (overlaps k_fill on the other stream) ---------------
__global__ void __launch_bounds__(256) k_gemm1(const float* __restrict__ x) {
    gemm_body<HH, 1>(x, blockIdx.x * 64);
}

// ---------------- GEMM2 + pool zeroing (one extra trivial block) ------------
__global__ void __launch_bounds__(256) k_gemm2(void) {
    if (blockIdx.x < GB1) {
        gemm_body<HO, 2>(nullptr, blockIdx.x * 64);
    } else {
        for (int j = threadIdx.x; j < NG * HO; j += 256) g_pool[j] = 0.f;
    }
}

// ---------------- aggregation 1 (gather-sum fp16, 128 feats) + bias/drop/relu
__global__ void k_agg1(const float* __restrict__ c1b, const float* __restrict__ du) {
    int node = (blockIdx.x * blockDim.x + threadIdx.x) >> 5;
    int lane = threadIdx.x & 31;
    if (node >= NN) return;
    float di = g_dis[node];
    size_t base = (size_t)node * HH + lane * 4;
    uint2 rs = *(const uint2*)&g_h2[base];  // self loop term
    float2 f0 = __half22float2(*(__half2*)&rs.x);
    float2 f1 = __half22float2(*(__half2*)&rs.y);
    float ax = f0.x, ay = f0.y, az = f1.x, aw = f1.y;
    int b = g_rowptr[node];
    int e = b + g_deg[node];
    int t = b;
    for (; t + 8 <= e; t += 8) {
        int si[8];
#pragma unroll
        for (int q = 0; q < 8; q++) si[q] = g_col[t + q];
        uint2 r[8];
#pragma unroll
        for (int q = 0; q < 8; q++)
            r[q] = *(const uint2*)&g_h2[(size_t)si[q] * HH + lane * 4];
#pragma unroll
        for (int q = 0; q < 8; q++) {
            float2 a = __half22float2(*(__half2*)&r[q].x);
            float2 bb = __half22float2(*(__half2*)&r[q].y);
            ax += a.x; ay += a.y; az += bb.x; aw += bb.y;
        }
    }
    for (; t + 4 <= e; t += 4) {
        int s0 = g_col[t], s1 = g_col[t + 1], s2 = g_col[t + 2], s3 = g_col[t + 3];
        uint2 r0 = *(const uint2*)&g_h2[(size_t)s0 * HH + lane * 4];
        uint2 r1 = *(const uint2*)&g_h2[(size_t)s1 * HH + lane * 4];
        uint2 r2 = *(const uint2*)&g_h2[(size_t)s2 * HH + lane * 4];
        uint2 r3 = *(const uint2*)&g_h2[(size_t)s3 * HH + lane * 4];
        float2 a0 = __half22float2(*(__half2*)&r0.x), b0 = __half22float2(*(__half2*)&r0.y);
        float2 a1 = __half22float2(*(__half2*)&r1.x), b1 = __half22float2(*(__half2*)&r1.y);
        float2 a2 = __half22float2(*(__half2*)&r2.x), b2 = __half22float2(*(__half2*)&r2.y);
        float2 a3 = __half22float2(*(__half2*)&r3.x), b3 = __half22float2(*(__half2*)&r3.y);
        ax += (a0.x + a1.x) + (a2.x + a3.x);
        ay += (a0.y + a1.y) + (a2.y + a3.y);
        az += (b0.x + b1.x) + (b2.x + b3.x);
        aw += (b0.y + b1.y) + (b2.y + b3.y);
    }
    for (; t < e; t++) {
        int s = g_col[t];
        uint2 r = *(const uint2*)&g_h2[(size_t)s * HH + lane * 4];
        float2 a = __half22float2(*(__half2*)&r.x);
        float2 bq = __half22float2(*(__half2*)&r.y);
        ax += a.x; ay += a.y; az += bq.x; aw += bq.y;
    }
    int c0 = lane * 4;
    float4 bb = *(const float4*)&c1b[c0];
    float4 dd = *(const float4*)&du[(size_t)node * DD + c0];
    float o[4] = {di * ax + bb.x, di * ay + bb.y, di * az + bb.z, di * aw + bb.w};
    float d4[4] = {dd.x, dd.y, dd.z, dd.w};
#pragma unroll
    for (int q = 0; q < 4; q++) {
        float val = (d4[q] >= 0.5f) ? o[q] * 2.f : 0.f;
        o[q] = fmaxf(val, 0.f);
    }
    uint2 pk;
    __half2 h0 = __floats2half2_rn(o[0], o[1]);
    __half2 h1 = __floats2half2_rn(o[2], o[3]);
    pk.x = *(unsigned*)&h0;
    pk.y = *(unsigned*)&h1;
    *(uint2*)&g_h3[base] = pk;
}

// ---------------- aggregation 2 (fp16, 64 feats) + bias + fused mean-pool ----
#define NPW 8
__global__ void k_agg2(const float* __restrict__ c2b) {
    int w = (blockIdx.x * blockDim.x + threadIdx.x) >> 5;
    int lane = threadIdx.x & 31;
    int n0 = w * NPW;
    if (n0 >= NN) return;
    int n1 = min(n0 + NPW, NN);
    int c0 = lane * 2;
    float b0 = c2b[c0], b1 = c2b[c0 + 1];
    int curg = -1;
    float s0 = 0.f, s1 = 0.f;
    for (int node = n0; node < n1; node++) {
        float di = g_dis[node];
        float2 v = __half22float2(*(const __half2*)&g_h4[(size_t)node * HO + c0]);
        float a0 = v.x, a1 = v.y;
        int b = g_rowptr[node];
        int e = b + g_deg[node];
        int t = b;
        for (; t + 8 <= e; t += 8) {
            int si[8];
#pragma unroll
            for (int q = 0; q < 8; q++) si[q] = g_col[t + q];
            float2 u[8];
#pragma unroll
            for (int q = 0; q < 8; q++)
                u[q] = __half22float2(*(const __half2*)&g_h4[(size_t)si[q] * HO + c0]);
#pragma unroll
            for (int q = 0; q < 8; q++) { a0 += u[q].x; a1 += u[q].y; }
        }
        for (; t + 4 <= e; t += 4) {
            int x0 = g_col[t], x1 = g_col[t + 1], x2 = g_col[t + 2], x3 = g_col[t + 3];
            float2 u0 = __half22float2(*(const __half2*)&g_h4[(size_t)x0 * HO + c0]);
            float2 u1 = __half22float2(*(const __half2*)&g_h4[(size_t)x1 * HO + c0]);
            float2 u2 = __half22float2(*(const __half2*)&g_h4[(size_t)x2 * HO + c0]);
            float2 u3 = __half22float2(*(const __half2*)&g_h4[(size_t)x3 * HO + c0]);
            a0 += (u0.x + u1.x) + (u2.x + u3.x);
            a1 += (u0.y + u1.y) + (u2.y + u3.y);
        }
        for (; t < e; t++) {
            int s = g_col[t];
            float2 u = __half22float2(*(const __half2*)&g_h4[(size_t)s * HO + c0]);
            a0 += u.x; a1 += u.y;
        }
        float v0 = di * a0 + b0;
        float v1 = di * a1 + b1;
        int g = g_batch[node];
        if (g != curg) {
            if (curg >= 0) {
                atomicAdd(&g_pool[curg * HO + c0], s0);
                atomicAdd(&g_pool[curg * HO + c0 + 1], s1);
            }
            curg = g;
            s0 = 0.f; s1 = 0.f;
        }
        s0 += v0; s1 += v1;
    }
    if (curg >= 0) {
        atomicAdd(&g_pool[curg * HO + c0], s0);
        atomicAdd(&g_pool[curg * HO + c0 + 1], s1);
    }
}

// ---------------- final: (pool / cnt) @ lin2_w + lin2_b + restore invariants
__device__ __forceinline__ int d_lower_bound(int g) {
    int lo = 0, hi = NN;
    while (lo < hi) {
        int m = (lo + hi) >> 1;
        if (g_batch[m] < g) lo = m + 1; else hi = m;
    }
    return lo;
}

__global__ void k_final(const float* __restrict__ w2, const float* __restrict__ b2,
                        float* __restrict__ out) {
    int idx = blockIdx.x * blockDim.x + threadIdx.x;
    int st = gridDim.x * blockDim.x;
    // restore invariants for the next call (statics start zeroed)
    for (int j = idx; j < NN; j += st) g_deg[j] = 0;
    if (idx == 0) g_base_ctr = 0;
    if (idx < NG * NCLS) {
        int g = idx / NCLS, c = idx % NCLS;
        int cnt = d_lower_bound(g + 1) - d_lower_bound(g);
        float cf = (float)cnt;
        if (cf < 1.f) cf = 1.f;
        float inv = 1.f / cf;
        float s = 0.f;
        for (int j = 0; j < HO; j++) s += g_pool[g * HO + j] * inv * w2[j * NCLS + c];
        out[idx] = s + b2[c];
    }
}

// ---------------- host launcher (two-stream graph with event edges) ---------
extern "C" void kernel_launch(void* const* d_in, const int* in_sizes, int n_in,
                              void* d_out, int out_size) {
    const float* x = (const float*)d_in[0];
    const void* edge = d_in[1];
    const void* batch = d_in[2];
    int off = (n_in >= 13 && in_sizes[3] == 1) ? 1 : 0;
    const float* drop_u = (const float*)d_in[3 + off];
    const float* l1w = (const float*)d_in[4 + off];
    const float* l1b = (const float*)d_in[5 + off];
    const float* c1w = (const float*)d_in[6 + off];
    const float* c1b = (const float*)d_in[7 + off];
    const float* c2w = (const float*)d_in[8 + off];
    const float* c2b = (const float*)d_in[9 + off];
    const float* l2w = (const float*)d_in[10 + off];
    const float* l2b = (const float*)d_in[11 + off];
    float* out = (float*)d_out;
    long esz = in_sizes[1];
    long bsz = in_sizes[2];

    // Lazily created once (first call = correctness run, outside capture).
    // Same launches issued on every call -> deterministic work.
    static cudaStream_t s1 = nullptr;
    static cudaEvent_t evFork = nullptr, evFold = nullptr, evScan = nullptr,
                       evFill = nullptr;
    if (s1 == nullptr) {
        cudaStreamCreateWithFlags(&s1, cudaStreamNonBlocking);
        cudaEventCreateWithFlags(&evFork, cudaEventDisableTiming);
        cudaEventCreateWithFlags(&evFold, cudaEventDisableTiming);
        cudaEventCreateWithFlags(&evScan, cudaEventDisableTiming);
        cudaEventCreateWithFlags(&evFill, cudaEventDisableTiming);
    }

    // fork: s1 joins the (captured) main stream
    cudaEventRecord(evFork, 0);
    cudaStreamWaitEvent(s1, evFork, 0);

    // s1: weight fold (independent of graph preprocessing)
    k_fold<<<(FOLD_ITEMS + 255) / 256, 256, 0, s1>>>(l1w, l1b, c1w, c2w);
    cudaEventRecord(evFold, s1);

    // main: histogram+rank, then scan
    k_prep<<<2048, 256>>>(edge, esz, batch, bsz);
    k_scan<<<SCAN_BLOCKS, 1024>>>();
    cudaEventRecord(evScan, 0);

    // s1: CSR fill (needs scan) — overlaps gemm1 on main
    cudaStreamWaitEvent(s1, evScan, 0);
    k_fill<<<2048, 256, 0, s1>>>(edge, esz);
    cudaEventRecord(evFill, s1);

    // main: gemm1 (needs fold + scan, NOT fill)
    cudaStreamWaitEvent(0, evFold, 0);
    k_gemm1<<<GB1, 256>>>(x);

    // join fill, then the serial tail
    cudaStreamWaitEvent(0, evFill, 0);
    k_agg1<<<(NN + 7) / 8, 256>>>(c1b, drop_u);
    k_gemm2<<<GB1 + 1, 256>>>();
    {
        int warps = (NN + NPW - 1) / NPW;
        int blocks = (warps + 7) / 8;
        k_agg2<<<blocks, 256>>>(c2b);
    }
    k_final<<<512, 256>>>(l2w, l2b, out);
    (void)out_size;
}